// round 17
// baseline (speedup 1.0000x reference)
#include <cuda_runtime.h>
#include <cuda_fp16.h>
#include <cstdint>

// SeqClassLSTM via mma.sync fp16 (sm_103-portable).
// R17: delete the k8 bias/x MMA. The D cell (row, col n) is initialized in
// the FMA pipe: d = fmaf(wx[n], x[row], bias[n]) from a float4 smem table —
// tensor work/step drops 96->64 MMAs and each accumulator chain shortens
// from 3 chained MMAs to init->2 MMAs. bias/x now exact fp32 (was fp16-split
// in the k8 chunk). Keeps R16: register-resident recurrence (D-frag map ==
// A-frag map), fp16 cell state (measured cheap: 3.36->3.41e-4), 32 seqs/warp,
// single-fp16 W_hh, 0.5-prescaled i/f/o rows, tanh.approx.f16x2, occupancy 3.

using u32 = uint32_t;

constexpr int T = 128;
constexpr int SEQ_CTA = 128;   // 32 per warp

__device__ __forceinline__ u32 sm_addr(const void* p) {
    u32 a;
    asm("{ .reg .u64 t; cvta.to.shared.u64 t, %1; cvt.u32.u64 %0, t; }" : "=r"(a) : "l"(p));
    return a;
}
// pack two f32 -> half2 (u32); LOW half = first arg
__device__ __forceinline__ u32 packh(float lo, float hi) {
    __half2 t = __floats2half2_rn(lo, hi);
    return *reinterpret_cast<u32*>(&t);
}
__device__ __forceinline__ __half2 asH2(u32 v) { return *reinterpret_cast<__half2*>(&v); }
__device__ __forceinline__ u32 asU(__half2 v) { return *reinterpret_cast<u32*>(&v); }
__device__ __forceinline__ __half2 tanh_h2(__half2 v) {
    u32 r, a = asU(v);
    asm("tanh.approx.f16x2 %0, %1;" : "=r"(r) : "r"(a));
    return asH2(r);
}
__device__ __forceinline__ void lds128(u32 r[4], u32 a) {
    asm volatile("ld.shared.v4.b32 {%0,%1,%2,%3}, [%4];"
                 : "=r"(r[0]), "=r"(r[1]), "=r"(r[2]), "=r"(r[3]) : "r"(a));
}
__device__ __forceinline__ void mma16816(float d[4], const u32 a[4], u32 b0, u32 b1) {
    asm volatile("mma.sync.aligned.m16n8k16.row.col.f32.f16.f16.f32 "
                 "{%0,%1,%2,%3}, {%4,%5,%6,%7}, {%8,%9}, {%0,%1,%2,%3};"
                 : "+f"(d[0]), "+f"(d[1]), "+f"(d[2]), "+f"(d[3])
                 : "r"(a[0]), "r"(a[1]), "r"(a[2]), "r"(a[3]), "r"(b0), "r"(b1));
}

__global__ void __launch_bounds__(128, 3)
lstm_hmma(const float* __restrict__ x,
          const float* __restrict__ W_ih,
          const float* __restrict__ W_hh,
          const float* __restrict__ b_ih,
          const float* __restrict__ b_hh,
          const float* __restrict__ W_fc,
          const float* __restrict__ b_fc,
          float* __restrict__ out,
          int B)
{
    // Btab[tau*32 + lane][4]: W fragments (i/f/o rows prescaled 0.5). 8KB.
    __shared__ u32 Btab[16 * 32 * 4];
    // bw_s[tau*4 + cc] = {bias(col0), wx(col0), bias(col1), wx(col1)},
    // cols = 2cc, 2cc+1 of tile tau; same 0.5 prescale on i/f/o. 1KB.
    __shared__ __align__(16) float4 bw_s[64];
    __shared__ float wfc_s[64];
    __shared__ float bfc_s[2];

    const int tid = threadIdx.x;
    const int wid = tid >> 5, lane = tid & 31;

    // ---- weight-fragment table; gate g (==2) unscaled, i/f/o scaled 0.5 ----
    for (int i = tid; i < 16 * 32 * 4; i += 128) {
        const int j   = i & 3;
        const int ln  = (i >> 2) & 31;
        const int tau = i >> 7;
        const int gate = tau >> 2;
        const float s = (gate == 2) ? 1.0f : 0.5f;
        const int n = tau * 8 + (ln >> 2);
        const int k = ((j >> 1) * 16) + ((j & 1) * 8) + 2 * (ln & 3);
        Btab[i] = packh(s * W_hh[n * 32 + k], s * W_hh[n * 32 + k + 1]);
    }
    // ---- bias/wx table (exact fp32) ----
    if (tid < 64) {
        const int tau = tid >> 2, c4 = tid & 3;
        const int gate = tau >> 2;
        const float s = (gate == 2) ? 1.0f : 0.5f;
        const int n0 = tau * 8 + 2 * c4;
        const int n1 = n0 + 1;
        bw_s[tid] = make_float4(s * (b_ih[n0] + b_hh[n0]), s * W_ih[n0],
                                s * (b_ih[n1] + b_hh[n1]), s * W_ih[n1]);
    }
    if (tid < 64) wfc_s[tid] = W_fc[tid];
    if (tid < 2) bfc_s[tid] = b_fc[tid];
    __syncthreads();

    const u32 btb = sm_addr(Btab);
    const u32 bwb = sm_addr(bw_s);
    const int cc = lane & 3;

    // each lane owns x of seq-in-warp = lane
    const int seqr = blockIdx.x * SEQ_CTA + wid * 32 + lane;
    const bool sv = (seqr < B);

    // h state: A fragments, register-resident. A0 = hid 0-15, A1 = hid 16-31.
    u32 A0[2][4], A1[2][4];
#pragma unroll
    for (int rb = 0; rb < 2; ++rb)
#pragma unroll
        for (int j = 0; j < 4; ++j) { A0[rb][j] = 0u; A1[rb][j] = 0u; }

    // fp16 cell state: cst[(rb*2+pr)*4 + q] covers (row, 2 cols)
    __half2 cst[16];
#pragma unroll
    for (int i = 0; i < 16; ++i) cst[i] = __floats2half2_rn(0.0f, 0.0f);

    const __half2 H05 = __floats2half2_rn(0.5f, 0.5f);
    const int srow = lane >> 2;   // fragment row r (0-7)

    float xcur = sv ? __ldg(&x[(size_t)seqr * T]) : 0.0f;

#pragma unroll 1
    for (int t = 0; t < T; ++t) {
        const float xnext = (sv && (t + 1) < T) ? __ldg(&x[(size_t)seqr * T + t + 1]) : 0.0f;

#pragma unroll
        for (int rb = 0; rb < 2; ++rb) {
            const float xa  = __shfl_sync(0xffffffffu, xcur, rb * 16 + srow);
            const float xbv = __shfl_sync(0xffffffffu, xcur, rb * 16 + srow + 8);

            u32 n0[4], n1[4];
#pragma unroll
            for (int q = 0; q < 4; ++q) {
                float dd[4][4];
#pragma unroll
                for (int gate = 0; gate < 4; ++gate) {
                    const int tau = q + gate * 4;
                    u32 bh[4];
                    lds128(bh, btb + (u32)(tau * 32 + lane) * 16u);
                    u32 bwu[4];
                    lds128(bwu, bwb + (u32)(tau * 4 + cc) * 16u);
                    const float b0 = __uint_as_float(bwu[0]);
                    const float w0 = __uint_as_float(bwu[1]);
                    const float b1 = __uint_as_float(bwu[2]);
                    const float w1 = __uint_as_float(bwu[3]);
                    float* d = dd[gate];
                    d[0] = fmaf(w0, xa,  b0);
                    d[1] = fmaf(w1, xa,  b1);
                    d[2] = fmaf(w0, xbv, b0);
                    d[3] = fmaf(w1, xbv, b1);
                    mma16816(d, A0[rb], bh[0], bh[1]);
                    mma16816(d, A1[rb], bh[2], bh[3]);
                }
#pragma unroll
                for (int pr = 0; pr < 2; ++pr) {
                    const int e = 2 * pr;
                    const __half2 iv = asH2(packh(dd[0][e], dd[0][e + 1]));
                    const __half2 fv = asH2(packh(dd[1][e], dd[1][e + 1]));
                    const __half2 gv = asH2(packh(dd[2][e], dd[2][e + 1]));
                    const __half2 ov = asH2(packh(dd[3][e], dd[3][e + 1]));
                    const __half2 si = __hfma2(tanh_h2(iv), H05, H05);
                    const __half2 sf = __hfma2(tanh_h2(fv), H05, H05);
                    const __half2 tg = tanh_h2(gv);
                    const __half2 so = __hfma2(tanh_h2(ov), H05, H05);
                    const __half2 p = __hmul2(si, tg);
                    const int ci = (rb * 2 + pr) * 4 + q;
                    const __half2 cn = __hfma2(sf, cst[ci], p);   // fp16 c update
                    cst[ci] = cn;
                    const u32 hv = asU(__hmul2(so, tanh_h2(cn)));
                    // D-frag == A-frag identity: route into next step's A regs
                    if (q == 0)      n0[pr]     = hv;
                    else if (q == 1) n0[2 + pr] = hv;
                    else if (q == 2) n1[pr]     = hv;
                    else             n1[2 + pr] = hv;
                }
            }
#pragma unroll
            for (int j = 0; j < 4; ++j) { A0[rb][j] = n0[j]; A1[rb][j] = n1[j]; }
        }
        xcur = xnext;
    }

    // ---- FC directly from h registers ----
#pragma unroll
    for (int rb = 0; rb < 2; ++rb) {
        float acc[2][2] = {{0.0f, 0.0f}, {0.0f, 0.0f}};
#pragma unroll
        for (int part = 0; part < 2; ++part) {
#pragma unroll
            for (int j = 0; j < 4; ++j) {
                const u32 v = part ? A1[rb][j] : A0[rb][j];
                const int rg = j & 1;                       // 0: rows r, 1: rows r+8
                const int hid = part * 16 + (j >> 1) * 8 + 2 * cc;
                const __half2 hh = asH2(v);
                const float h0 = __low2float(hh);
                const float h1 = __high2float(hh);
                acc[rg][0] = fmaf(h0, wfc_s[hid],      fmaf(h1, wfc_s[hid + 1],      acc[rg][0]));
                acc[rg][1] = fmaf(h0, wfc_s[32 + hid], fmaf(h1, wfc_s[32 + hid + 1], acc[rg][1]));
            }
        }
#pragma unroll
        for (int rg = 0; rg < 2; ++rg)
#pragma unroll
            for (int o = 0; o < 2; ++o) {
                acc[rg][o] += __shfl_xor_sync(0xffffffffu, acc[rg][o], 1);
                acc[rg][o] += __shfl_xor_sync(0xffffffffu, acc[rg][o], 2);
            }
        if (cc == 0) {
            const int s0 = blockIdx.x * SEQ_CTA + wid * 32 + rb * 16 + srow;
            if (s0 < B) {
                out[(size_t)s0 * 2 + 0] = acc[0][0] + bfc_s[0];
                out[(size_t)s0 * 2 + 1] = acc[0][1] + bfc_s[1];
            }
            const int s1 = s0 + 8;
            if (s1 < B) {
                out[(size_t)s1 * 2 + 0] = acc[1][0] + bfc_s[0];
                out[(size_t)s1 * 2 + 1] = acc[1][1] + bfc_s[1];
            }
        }
    }
}

extern "C" void kernel_launch(void* const* d_in, const int* in_sizes, int n_in,
                              void* d_out, int out_size)
{
    const float* x    = (const float*)d_in[0];
    const float* W_ih = (const float*)d_in[1];
    const float* W_hh = (const float*)d_in[2];
    const float* b_ih = (const float*)d_in[3];
    const float* b_hh = (const float*)d_in[4];
    const float* W_fc = (const float*)d_in[5];
    const float* b_fc = (const float*)d_in[6];
    float* out = (float*)d_out;

    const int B = in_sizes[0] / T;                // x has B*T elements
    const int blocks = (B + SEQ_CTA - 1) / SEQ_CTA;

    lstm_hmma<<<blocks, 128>>>(x, W_ih, W_hh, b_ih, b_hh, W_fc, b_fc, out, B);
}